// round 15
// baseline (speedup 1.0000x reference)
#include <cuda_runtime.h>
#include <cuda_fp16.h>
#include <cstdint>

// ============================================================================
// y[128, 11008] = x[128,4096] @ W[11008,4096]^T * scale + bias
// w_q arrives as int32 (harness widens int8 -> int32).
// fp16 single-pass: x -> fp16 (rel err ~2e-4), W int8 exact in fp16.
// mma.sync.m16n8k16 + ldmatrix fragments.
// R13: W path fully through cp.async. B32 ring (3 stages, cp.async) ->
// in-smem convert pass -> Bf16 double buffer. No W registers held.
// CTA 128(M) x 40(N), 128 thr, warp tile 32x40, grid 276, 2 CTAs/SM.
// K_STAGE=64 (64 steps). Two commit groups per step; wait_group<1> pins
// A(s) + B32(s+1), lets B32(s+2) fly -> continuous DRAM streaming.
// ============================================================================

#define M_ROWS 128
#define K_DIM  4096
#define N_DIM  11008
#define N_TILE 40
#define N_BLOCKS ((N_DIM + N_TILE - 1) / N_TILE)   // 276
#define K_STAGE 64                         // k elements per stage
#define NUM_STEPS (K_DIM / K_STAGE)        // 64
#define NTHREADS 128

// smem layout (per CTA):
//   A fp16   : 2 stages x 128 rows x 144B (128 data + 16 pad)
//   Bf16     : 2 stages x  40 rows x 144B
//   B32 ring : 3 slots  x  40 rows x 272B (256 data + 16 pad)
#define A_PITCH   144
#define A_TILE    (M_ROWS * A_PITCH)       // 18432
#define BF_PITCH  144
#define BF_TILE   (N_TILE * BF_PITCH)      // 5760
#define B32_PITCH 272
#define B32_TILE  (N_TILE * B32_PITCH)     // 10880
#define BF_BASE   (2 * A_TILE)             // 36864
#define B32_BASE  (BF_BASE + 2 * BF_TILE)  // 48384
#define SMEM_TOTAL (B32_BASE + 3 * B32_TILE) // 81024 -> 2 CTAs/SM

// ---- scratch (no cudaMalloc allowed) ----
__device__ __align__(1024) __half g_xh[M_ROWS * K_DIM];

// ============================================================================
// helpers
// ============================================================================
__device__ __forceinline__ uint32_t smem_u32(const void* p) {
    uint32_t a;
    asm("{ .reg .u64 t; cvta.to.shared.u64 t, %1; cvt.u32.u64 %0, t; }"
        : "=r"(a) : "l"(p));
    return a;
}
__device__ __forceinline__ void cp16(uint32_t dst, const void* src) {
    asm volatile("cp.async.cg.shared.global [%0], [%1], 16;"
                 :: "r"(dst), "l"(src) : "memory");
}
__device__ __forceinline__ void cp_commit() {
    asm volatile("cp.async.commit_group;" ::: "memory");
}
template <int N>
__device__ __forceinline__ void cp_wait() {
    asm volatile("cp.async.wait_group %0;" :: "n"(N) : "memory");
}
__device__ __forceinline__ void ldsm_x4(uint32_t* r, uint32_t addr) {
    asm volatile("ldmatrix.sync.aligned.m8n8.x4.shared.b16 {%0,%1,%2,%3}, [%4];"
                 : "=r"(r[0]), "=r"(r[1]), "=r"(r[2]), "=r"(r[3]) : "r"(addr));
}
__device__ __forceinline__ void ldsm_x2(uint32_t* r, uint32_t addr) {
    asm volatile("ldmatrix.sync.aligned.m8n8.x2.shared.b16 {%0,%1}, [%2];"
                 : "=r"(r[0]), "=r"(r[1]) : "r"(addr));
}
__device__ __forceinline__ void mma_f16(float* d, const uint32_t* a, const uint32_t* b) {
    asm volatile(
        "mma.sync.aligned.m16n8k16.row.col.f32.f16.f16.f32 "
        "{%0,%1,%2,%3}, {%4,%5,%6,%7}, {%8,%9}, {%0,%1,%2,%3};"
        : "+f"(d[0]), "+f"(d[1]), "+f"(d[2]), "+f"(d[3])
        : "r"(a[0]), "r"(a[1]), "r"(a[2]), "r"(a[3]), "r"(b[0]), "r"(b[1]));
}
__device__ __forceinline__ uint32_t i2h2(int lo, int hi) {
    __half2 h = __halves2half2(__int2half_rn(lo), __int2half_rn(hi));
    return *reinterpret_cast<uint32_t*>(&h);
}

// ============================================================================
// Kernel 1: x (fp32) -> fp16
// ============================================================================
__global__ __launch_bounds__(512) void cvt_x_kernel(const float* __restrict__ x) {
    int idx = (blockIdx.x * 512 + threadIdx.x) * 8;
    float4 v0 = *reinterpret_cast<const float4*>(x + idx);
    float4 v1 = *reinterpret_cast<const float4*>(x + idx + 4);
    __half2 h[4];
    h[0] = __floats2half2_rn(v0.x, v0.y);
    h[1] = __floats2half2_rn(v0.z, v0.w);
    h[2] = __floats2half2_rn(v1.x, v1.y);
    h[3] = __floats2half2_rn(v1.z, v1.w);
    *reinterpret_cast<uint4*>(g_xh + idx) = *reinterpret_cast<uint4*>(h);
}

// ============================================================================
// Kernel 2: GEMM. 276 CTAs x 128 threads, 2 CTAs/SM. CTA tile 128(M) x 40(N).
// 4 warps, warp tile 32x40.
// Per step s: wait<1>; sync; convert B32(s+1)->Bf16; issueA(s+1);
//             issueB32(s+3); 4 x k16 MMA block on A(s)/Bf16(s).
// Each thread converts exactly the chunks it cp'd (same index formula),
// so own-thread wait_group suffices for B32; the barrier publishes A + Bf16.
// ============================================================================
__global__ void __launch_bounds__(NTHREADS, 2) gemm_f16_kernel(
    const int* __restrict__ w32,
    const float* __restrict__ scale,
    const float* __restrict__ bias,
    float* __restrict__ out)
{
    extern __shared__ char smem[];
    const uint32_t sb = smem_u32(smem);
    const int tid = threadIdx.x;
    const int lane = tid & 31;
    const int wid = tid >> 5;          // warp M index (0..3)
    const int n_base = blockIdx.x * N_TILE;

    // ---- A: 8 x 16B cp.async chunks per thread per stage (16KB) ------------
    auto issueA = [&](int s) {
        const uint32_t base = sb + (uint32_t)((s & 1) * A_TILE);
        const int k0h = s * K_STAGE;     // fp16 element offset
#pragma unroll
        for (int i = 0; i < 8; i++) {
            int c = tid + i * 128;       // [0, 1024)
            int r = c >> 3;              // m row 0..127
            int col = (c & 7) * 16;      // byte col 0..112
            cp16(base + r * A_PITCH + col,
                 g_xh + (size_t)r * K_DIM + k0h + col / 2);
        }
        cp_commit();
    };

    // ---- B32: 5 x 16B cp.async chunks per thread per stage (10KB) ----------
    auto issueB = [&](int s) {
        const uint32_t base = sb + (uint32_t)(B32_BASE + (s % 3) * B32_TILE);
        const int k0 = s * K_STAGE;      // int32 element offset
#pragma unroll
        for (int i = 0; i < 5; i++) {
            int c = tid + i * 128;       // [0, 640)
            int r = c >> 4;              // n row 0..39
            int col = (c & 15) * 16;     // byte col 0..240
            int rg = n_base + r;
            if (rg > N_DIM - 1) rg = N_DIM - 1;   // clamp (ragged last tile)
            cp16(base + r * B32_PITCH + col,
                 w32 + (size_t)rg * K_DIM + k0 + col / 4);
        }
        cp_commit();
    };

    // ---- convert: B32 slot (s%3) -> Bf16 buffer (s&1), own chunks ----------
    auto convertB = [&](int s) {
        const char* src = smem + B32_BASE + (s % 3) * B32_TILE;
        char* dst = smem + BF_BASE + (s & 1) * BF_TILE;
#pragma unroll
        for (int i = 0; i < 5; i++) {
            int c = tid + i * 128;
            int r = c >> 4;
            int col = (c & 15) * 16;
            int4 v = *reinterpret_cast<const int4*>(src + r * B32_PITCH + col);
            uint2 hv;
            hv.x = i2h2(v.x, v.y);
            hv.y = i2h2(v.z, v.w);
            *reinterpret_cast<uint2*>(dst + r * BF_PITCH + col / 2) = hv;
        }
    };

    // ---- prologue ----------------------------------------------------------
    issueA(0);                      // group: A(0)
    issueB(0); issueB(1); issueB(2);// groups: B(0), B(1), B(2)
    cp_wait<1>();                   // A(0), B(0), B(1) done; B(2) in flight
    convertB(0);                    // Bf16(0) ready (own chunks)

    // ---- ldmatrix per-lane addresses (offsets within buffers) --------------
    const int aRow  = lane & 15;
    const int aKoff = (lane >> 4) * 16;
    const int bRow  = (lane & 7) | ((lane >> 4) << 3);
    const int bKoff = ((lane >> 3) & 1) * 16;
    const uint32_t aOff  = (uint32_t)((wid * 32 + aRow) * A_PITCH + aKoff);
    const uint32_t bOff  = (uint32_t)(bRow * BF_PITCH + bKoff);
    const uint32_t bOff2 = (uint32_t)((32 + (lane & 7)) * BF_PITCH
                                      + ((lane >> 3) & 1) * 16);

    float acc[2][5][4] = {};

    // ---- main loop ---------------------------------------------------------
    for (int s = 0; s < NUM_STEPS; s++) {
        cp_wait<1>();          // pins A(s) + B32(s+1); B32(s+2) may fly
        __syncthreads();       // publish A(s) + Bf16(s) cross-thread

        if (s + 1 < NUM_STEPS) { convertB(s + 1); issueA(s + 1); }
        else                   { cp_commit(); }                 // pad A slot
        if (s + 3 < NUM_STEPS) issueB(s + 3);
        else                   cp_commit();                     // pad B slot

        const uint32_t aBase = sb + (uint32_t)((s & 1) * A_TILE) + aOff;
        const uint32_t bBase = sb + (uint32_t)(BF_BASE + (s & 1) * BF_TILE);
        const uint32_t bA  = bBase + bOff;
        const uint32_t bA2 = bBase + bOff2;

        uint32_t af[2][2][4], bf[2][10];
        ldsm_x4(af[0][0], aBase);
        ldsm_x4(af[0][1], aBase + 16 * A_PITCH);
        ldsm_x4(bf[0],     bA);
        ldsm_x4(bf[0] + 4, bA + 16 * BF_PITCH);
        ldsm_x2(bf[0] + 8, bA2);

#pragma unroll
        for (int ks = 0; ks < 4; ks++) {          // 4 x k16 per stage
            if (ks < 3) {
                const uint32_t off = (ks + 1) * 32;
                ldsm_x4(af[(ks + 1) & 1][0], aBase + off);
                ldsm_x4(af[(ks + 1) & 1][1], aBase + off + 16 * A_PITCH);
                ldsm_x4(bf[(ks + 1) & 1],     bA + off);
                ldsm_x4(bf[(ks + 1) & 1] + 4, bA + off + 16 * BF_PITCH);
                ldsm_x2(bf[(ks + 1) & 1] + 8, bA2 + off);
            }
#pragma unroll
            for (int mf = 0; mf < 2; mf++)
#pragma unroll
                for (int j = 0; j < 5; j++)
                    mma_f16(acc[mf][j], af[ks & 1][mf], bf[ks & 1] + 2 * j);
        }
    }

    // ---- epilogue ----------------------------------------------------------
    const float sw = __ldg(scale);
    const int g = lane >> 2;
    const int mrow0 = wid * 32 + g;
#pragma unroll
    for (int mf = 0; mf < 2; mf++) {
        int m0 = mrow0 + mf * 16;
#pragma unroll
        for (int j = 0; j < 5; j++) {
            int n = n_base + j * 8 + 2 * (lane & 3);
            if (n < N_DIM) {
                float2 bv = __ldg(reinterpret_cast<const float2*>(bias + n));
                float2 o0, o1;
                o0.x = acc[mf][j][0] * sw + bv.x;
                o0.y = acc[mf][j][1] * sw + bv.y;
                o1.x = acc[mf][j][2] * sw + bv.x;
                o1.y = acc[mf][j][3] * sw + bv.y;
                *reinterpret_cast<float2*>(out + (size_t)m0 * N_DIM + n) = o0;
                *reinterpret_cast<float2*>(out + (size_t)(m0 + 8) * N_DIM + n) = o1;
            }
        }
    }
}

// ============================================================================
// Host launcher — inputs identified by element count (order-robust)
// ============================================================================
extern "C" void kernel_launch(void* const* d_in, const int* in_sizes, int n_in,
                              void* d_out, int out_size) {
    const float* x     = nullptr;
    const int*   w32   = nullptr;    // int8 weights widened to int32 by harness
    const float* scale = nullptr;
    const float* bias  = nullptr;
    for (int i = 0; i < n_in; i++) {
        switch (in_sizes[i]) {
            case M_ROWS * K_DIM: x     = (const float*)d_in[i]; break;  // 524288
            case N_DIM * K_DIM:  w32   = (const int*)d_in[i];   break;  // 45088768
            case 1:              scale = (const float*)d_in[i]; break;
            case N_DIM:          bias  = (const float*)d_in[i]; break;  // 11008
        }
    }
    float* out = (float*)d_out;

    cudaFuncSetAttribute(gemm_f16_kernel,
                         cudaFuncAttributeMaxDynamicSharedMemorySize, SMEM_TOTAL);

    cvt_x_kernel<<<M_ROWS, 512>>>(x);
    gemm_f16_kernel<<<N_BLOCKS, NTHREADS, SMEM_TOTAL>>>(w32, scale, bias, out);
}